// round 2
// baseline (speedup 1.0000x reference)
#include <cuda_runtime.h>
#include <cuda_bf16.h>
#include <stdint.h>

// ============================================================================
// GumbelTopK: exact global k-select (radix, 12+20 bit) + elementwise gumbel
// passes. Graph-capturable: all inter-phase control flow via __device__ globals.
// R2: fused candidate collection into hist2 (kills a 64MB pass), warp-aggregated
// atomics, streaming cache hints.
// ============================================================================

#define N_MAX   (1u << 24)       // 4096*4096
#define H1_BINS 4096             // top 12 bits
#define H2_BINS (1u << 20)       // low 20 bits
#define TIE_CAP (1u << 20)
#define EPSF    1e-8f

__device__ unsigned int g_keys[N_MAX];
__device__ uint2        g_cand[N_MAX];     // {low20 key, idx} of selected-prefix elems
__device__ unsigned int g_hist1[H1_BINS];
__device__ unsigned int g_hist2[H2_BINS];
__device__ unsigned int g_csum2[1024];
__device__ int          g_tie_idx[TIE_CAP];
__device__ unsigned int g_tie_cnt;
__device__ unsigned int g_cand_cnt;
__device__ unsigned int g_prefix12;
__device__ unsigned int g_k1;
__device__ unsigned int g_T;
__device__ unsigned int g_r;
__device__ int          g_cutoff;

__device__ __forceinline__ float gum(float u) {
    return -logf(-logf(u + EPSF) + EPSF);
}

__device__ __forceinline__ unsigned int f2key(float f) {
    unsigned int b = __float_as_uint(f);
    return (b & 0x80000000u) ? ~b : (b | 0x80000000u);
}

// warp-aggregated smem histogram add: collapse same-bin lanes to one atomic
__device__ __forceinline__ void agg_add(unsigned int* sh, unsigned int bin) {
    unsigned int am = __activemask();
    unsigned int m = __match_any_sync(am, bin);
    int leader = __ffs(m) - 1;
    if ((int)(threadIdx.x & 31) == leader) atomicAdd(&sh[bin], __popc(m));
}

// ---------------------------------------------------------------------------
__global__ void reset_k() {
    int stride = gridDim.x * blockDim.x;
    for (unsigned int i = blockIdx.x * blockDim.x + threadIdx.x; i < H2_BINS; i += stride)
        g_hist2[i] = 0;
    unsigned int t = blockIdx.x * blockDim.x + threadIdx.x;
    if (t < H1_BINS) g_hist1[t] = 0;
    if (t == 0) { g_tie_cnt = 0; g_cand_cnt = 0; }
}

// ---------------------------------------------------------------------------
// pass A: score + key store + 12-bit histogram (smem, warp-aggregated)
// ---------------------------------------------------------------------------
__global__ void __launch_bounds__(256) score_hist_k(
        const float* __restrict__ logits,
        const float* __restrict__ u1,
        const int* __restrict__ training, int n4) {
    __shared__ unsigned int sh[H1_BINS];
    for (int i = threadIdx.x; i < H1_BINS; i += blockDim.x) sh[i] = 0;
    __syncthreads();
    const int tr = *training;
    const int stride = gridDim.x * blockDim.x;
    for (int i = blockIdx.x * blockDim.x + threadIdx.x; i < n4; i += stride) {
        float4 l = __ldcs((const float4*)logits + i);
        float4 u = __ldcs((const float4*)u1 + i);
        float s0 = tr ? (l.x + gum(u.x)) : l.x;
        float s1 = tr ? (l.y + gum(u.y)) : l.y;
        float s2 = tr ? (l.z + gum(u.z)) : l.z;
        float s3 = tr ? (l.w + gum(u.w)) : l.w;
        uint4 kk;
        kk.x = f2key(s0); kk.y = f2key(s1); kk.z = f2key(s2); kk.w = f2key(s3);
        ((uint4*)g_keys)[i] = kk;               // keep resident in L2 for hist2
        agg_add(sh, kk.x >> 20);
        agg_add(sh, kk.y >> 20);
        agg_add(sh, kk.z >> 20);
        agg_add(sh, kk.w >> 20);
    }
    __syncthreads();
    for (int i = threadIdx.x; i < H1_BINS; i += blockDim.x) {
        unsigned int c = sh[i];
        if (c) atomicAdd(&g_hist1[i], c);
    }
}

// ---------------------------------------------------------------------------
__device__ __forceinline__ unsigned int block_incl_scan(unsigned int v, unsigned int* sh) {
    int t = threadIdx.x;
    sh[t] = v;
    __syncthreads();
    for (int off = 1; off < blockDim.x; off <<= 1) {
        unsigned int add = (t >= off) ? sh[t - off] : 0u;
        __syncthreads();
        sh[t] += add;
        __syncthreads();
    }
    return sh[t];
}

// select level 1: 12-bit bin holding rank-k (descending)
__global__ void select1_k(const int* __restrict__ kp) {
    __shared__ unsigned int sh[1024];
    const unsigned int k = (unsigned int)(*kp);
    int t = threadIdx.x;
    unsigned int c[4], s = 0;
#pragma unroll
    for (int j = 0; j < 4; j++) { c[j] = g_hist1[4095 - (4 * t + j)]; s += c[j]; }
    unsigned int incl = block_incl_scan(s, sh);
    unsigned int excl = incl - s;
    if (excl < k && k <= incl) {
        unsigned int cum = excl;
#pragma unroll
        for (int j = 0; j < 4; j++) {
            if (cum + c[j] >= k) { g_prefix12 = 4095 - (4 * t + j); g_k1 = k - cum; break; }
            cum += c[j];
        }
    }
}

// ---------------------------------------------------------------------------
// pass B: 20-bit histogram inside selected bin + candidate collection (fused)
// ---------------------------------------------------------------------------
__device__ __forceinline__ void push_cand(unsigned int low, unsigned int idx, bool pred) {
    unsigned int am = __activemask();
    unsigned int vote = __ballot_sync(am, pred);
    if (!vote) return;
    unsigned int base = 0;
    int leader = __ffs(vote) - 1;
    if ((int)(threadIdx.x & 31) == leader)
        base = atomicAdd(&g_cand_cnt, (unsigned int)__popc(vote));
    base = __shfl_sync(am, base, leader);
    if (pred) {
        unsigned int off = __popc(vote & (((unsigned int)1 << (threadIdx.x & 31)) - 1u));
        g_cand[base + off] = make_uint2(low, idx);
    }
}

__global__ void __launch_bounds__(256) hist2_k(int n4) {
    const unsigned int pfx = g_prefix12;
    const int stride = gridDim.x * blockDim.x;
    for (int i = blockIdx.x * blockDim.x + threadIdx.x; i < n4; i += stride) {
        uint4 kk = ((const uint4*)g_keys)[i];
#pragma unroll
        for (int j = 0; j < 4; j++) {
            unsigned int key = (j == 0) ? kk.x : (j == 1) ? kk.y : (j == 2) ? kk.z : kk.w;
            bool hit = (key >> 20) == pfx;
            unsigned int low = key & 0xFFFFFu;
            if (hit) atomicAdd(&g_hist2[low], 1u);
            push_cand(low, 4 * i + j, hit);
        }
    }
}

// chunk sums of hist2 (1024 chunks of 1024 bins)
__global__ void chunksum2_k() {
    __shared__ unsigned int sh[256];
    int b = blockIdx.x;
    unsigned int s = 0;
    for (int j = threadIdx.x; j < 1024; j += 256) s += g_hist2[b * 1024 + j];
    sh[threadIdx.x] = s;
    __syncthreads();
    for (int off = 128; off > 0; off >>= 1) {
        if (threadIdx.x < off) sh[threadIdx.x] += sh[threadIdx.x + off];
        __syncthreads();
    }
    if (threadIdx.x == 0) g_csum2[b] = sh[0];
}

// select level 2: exact threshold key T and r = #(==T) to include
__global__ void select2_k() {
    __shared__ unsigned int sh[1024];
    __shared__ unsigned int s_chunk, s_k2;
    int t = threadIdx.x;
    const unsigned int k1 = g_k1;
    unsigned int s = g_csum2[1023 - t];
    unsigned int incl = block_incl_scan(s, sh);
    unsigned int excl = incl - s;
    if (excl < k1 && k1 <= incl) { s_chunk = 1023 - t; s_k2 = k1 - excl; }
    __syncthreads();
    const unsigned int a = s_chunk;
    const unsigned int k2 = s_k2;
    unsigned int bin = a * 1024 + 1023 - t;
    unsigned int cb = g_hist2[bin];
    __syncthreads();
    unsigned int incl2 = block_incl_scan(cb, sh);
    unsigned int excl2 = incl2 - cb;
    if (excl2 < k2 && k2 <= incl2) {
        g_T = (g_prefix12 << 20) | bin;
        g_r = k2 - excl2;
    }
}

// ---------------------------------------------------------------------------
// tie filter: scan candidate list (small), emit indices with key == T
// ---------------------------------------------------------------------------
__global__ void tie_filter_k() {
    const unsigned int T20 = g_T & 0xFFFFFu;
    const unsigned int m = min(g_cand_cnt, (unsigned int)N_MAX);
    const unsigned int stride = gridDim.x * blockDim.x;
    for (unsigned int i = blockIdx.x * blockDim.x + threadIdx.x; i < m; i += stride) {
        uint2 c = g_cand[i];
        if (c.x == T20) {
            unsigned int p = atomicAdd(&g_tie_cnt, 1u);
            if (p < TIE_CAP) g_tie_idx[p] = (int)c.y;
        }
    }
}

// r-th smallest tie index -> cutoff
__global__ void select_idx_k(int n) {
    __shared__ int s_cnt;
    unsigned int m = g_tie_cnt;
    if (m > TIE_CAP) m = TIE_CAP;
    const unsigned int r = g_r;
    if (r >= m) { if (threadIdx.x == 0) g_cutoff = 0x7FFFFFFF; return; }
    int lo = 0, hi = n - 1;
    while (lo < hi) {
        int mid = lo + (hi - lo) / 2;
        if (threadIdx.x == 0) s_cnt = 0;
        __syncthreads();
        int c = 0;
        for (unsigned int j = threadIdx.x; j < m; j += blockDim.x)
            if (g_tie_idx[j] <= mid) c++;
        atomicAdd(&s_cnt, c);
        __syncthreads();
        if (s_cnt >= (int)r) hi = mid; else lo = mid + 1;
        __syncthreads();
    }
    if (threadIdx.x == 0) g_cutoff = lo;
}

// ---------------------------------------------------------------------------
// pass D: final output
// ---------------------------------------------------------------------------
__device__ __forceinline__ float out_elem(unsigned int key, int idx, float u0, float u1,
                                          unsigned int T, int cutoff, int tr) {
    float m = (key > T || (key == T && idx <= cutoff)) ? 1.0f : 0.0f;
    if (!tr) return m;
    float g0 = gum(u0);
    float g1 = gum(u1);
    return (m + g1 > g0) ? 1.0f : 0.0f;
}

__global__ void __launch_bounds__(256) final_k(
        const float* __restrict__ u2,
        const int* __restrict__ training,
        float* __restrict__ out, int n4) {
    const unsigned int T = g_T;
    const int cutoff = g_cutoff;
    const int tr = *training;
    const int stride = gridDim.x * blockDim.x;
    for (int i = blockIdx.x * blockDim.x + threadIdx.x; i < n4; i += stride) {
        uint4 kk = __ldcs((const uint4*)g_keys + i);
        float4 a = __ldcs((const float4*)u2 + 2 * i);
        float4 b = __ldcs((const float4*)u2 + 2 * i + 1);
        float4 o;
        o.x = out_elem(kk.x, 4 * i + 0, a.x, a.y, T, cutoff, tr);
        o.y = out_elem(kk.y, 4 * i + 1, a.z, a.w, T, cutoff, tr);
        o.z = out_elem(kk.z, 4 * i + 2, b.x, b.y, T, cutoff, tr);
        o.w = out_elem(kk.w, 4 * i + 3, b.z, b.w, T, cutoff, tr);
        __stcs((float4*)out + i, o);
    }
}

// ---------------------------------------------------------------------------
extern "C" void kernel_launch(void* const* d_in, const int* in_sizes, int n_in,
                              void* d_out, int out_size) {
    const float* mask_logits = (const float*)d_in[0];
    const float* u1          = (const float*)d_in[1];
    const float* u2          = (const float*)d_in[2];
    const int*   kp          = (const int*)d_in[3];
    const int*   training    = (const int*)d_in[4];
    float* out = (float*)d_out;

    const int n  = in_sizes[0];
    const int n4 = n / 4;

    reset_k<<<1024, 256>>>();
    score_hist_k<<<2048, 256>>>(mask_logits, u1, training, n4);
    select1_k<<<1, 1024>>>(kp);
    hist2_k<<<2048, 256>>>(n4);
    chunksum2_k<<<1024, 256>>>();
    select2_k<<<1, 1024>>>();
    tie_filter_k<<<512, 256>>>();
    select_idx_k<<<1, 1024>>>(n);
    final_k<<<4096, 256>>>(u2, training, out, n4);
}

// round 3
// speedup vs baseline: 2.8408x; 2.8408x over previous
#include <cuda_runtime.h>
#include <cuda_bf16.h>
#include <stdint.h>

// ============================================================================
// GumbelTopK: exact global k-select (radix 12+20 bit) + gumbel passes.
// R3: no candidate collection at all — ties (key==T, ~1-5 elems) are recorded
// inside final_k for free, then a tiny fixup kernel corrects them. All big
// passes are bare streaming kernels with 2x uint4 unroll.
// ============================================================================

#define N_MAX   (1u << 24)       // 4096*4096
#define H1_BINS 4096             // top 12 bits
#define H2_BINS (1u << 20)       // low 20 bits
#define TIE_CAP 65536
#define EPSF    1e-8f

__device__ unsigned int g_keys[N_MAX];
__device__ unsigned int g_hist1[H1_BINS];
__device__ unsigned int g_hist2[H2_BINS];
__device__ unsigned int g_csum2[1024];
__device__ int          g_tie_idx[TIE_CAP];
__device__ unsigned int g_tie_cnt;
__device__ unsigned int g_prefix12;
__device__ unsigned int g_k1;
__device__ unsigned int g_T;
__device__ unsigned int g_r;

__device__ __forceinline__ float gum(float u) {
    return -logf(-logf(u + EPSF) + EPSF);
}

__device__ __forceinline__ unsigned int f2key(float f) {
    unsigned int b = __float_as_uint(f);
    return (b & 0x80000000u) ? ~b : (b | 0x80000000u);
}

// ---------------------------------------------------------------------------
__global__ void reset_k() {
    int stride = gridDim.x * blockDim.x;
    for (unsigned int i = blockIdx.x * blockDim.x + threadIdx.x; i < H2_BINS; i += stride)
        g_hist2[i] = 0;
    unsigned int t = blockIdx.x * blockDim.x + threadIdx.x;
    if (t < H1_BINS) g_hist1[t] = 0;
    if (t == 0) g_tie_cnt = 0;
}

// ---------------------------------------------------------------------------
// pass A: score + key store + 12-bit histogram (2x replicated smem hist)
// ---------------------------------------------------------------------------
__global__ void __launch_bounds__(256) score_hist_k(
        const float* __restrict__ logits,
        const float* __restrict__ u1,
        const int* __restrict__ training, int n4) {
    __shared__ unsigned int sh[2 * H1_BINS];
    for (int i = threadIdx.x; i < 2 * H1_BINS; i += blockDim.x) sh[i] = 0;
    __syncthreads();
    unsigned int* mysh = sh + ((threadIdx.x >> 5) & 1) * H1_BINS;
    const int tr = *training;
    const int stride = gridDim.x * blockDim.x;
    int i = blockIdx.x * blockDim.x + threadIdx.x;
    for (; i + stride < n4; i += 2 * stride) {
        float4 l0 = __ldcs((const float4*)logits + i);
        float4 u0 = __ldcs((const float4*)u1 + i);
        float4 l1 = __ldcs((const float4*)logits + i + stride);
        float4 u1v = __ldcs((const float4*)u1 + i + stride);
        uint4 k0, k1;
        k0.x = f2key(tr ? (l0.x + gum(u0.x)) : l0.x);
        k0.y = f2key(tr ? (l0.y + gum(u0.y)) : l0.y);
        k0.z = f2key(tr ? (l0.z + gum(u0.z)) : l0.z);
        k0.w = f2key(tr ? (l0.w + gum(u0.w)) : l0.w);
        k1.x = f2key(tr ? (l1.x + gum(u1v.x)) : l1.x);
        k1.y = f2key(tr ? (l1.y + gum(u1v.y)) : l1.y);
        k1.z = f2key(tr ? (l1.z + gum(u1v.z)) : l1.z);
        k1.w = f2key(tr ? (l1.w + gum(u1v.w)) : l1.w);
        ((uint4*)g_keys)[i] = k0;
        ((uint4*)g_keys)[i + stride] = k1;
        atomicAdd(&mysh[k0.x >> 20], 1u);
        atomicAdd(&mysh[k0.y >> 20], 1u);
        atomicAdd(&mysh[k0.z >> 20], 1u);
        atomicAdd(&mysh[k0.w >> 20], 1u);
        atomicAdd(&mysh[k1.x >> 20], 1u);
        atomicAdd(&mysh[k1.y >> 20], 1u);
        atomicAdd(&mysh[k1.z >> 20], 1u);
        atomicAdd(&mysh[k1.w >> 20], 1u);
    }
    for (; i < n4; i += stride) {
        float4 l = __ldcs((const float4*)logits + i);
        float4 u = __ldcs((const float4*)u1 + i);
        uint4 kk;
        kk.x = f2key(tr ? (l.x + gum(u.x)) : l.x);
        kk.y = f2key(tr ? (l.y + gum(u.y)) : l.y);
        kk.z = f2key(tr ? (l.z + gum(u.z)) : l.z);
        kk.w = f2key(tr ? (l.w + gum(u.w)) : l.w);
        ((uint4*)g_keys)[i] = kk;
        atomicAdd(&mysh[kk.x >> 20], 1u);
        atomicAdd(&mysh[kk.y >> 20], 1u);
        atomicAdd(&mysh[kk.z >> 20], 1u);
        atomicAdd(&mysh[kk.w >> 20], 1u);
    }
    __syncthreads();
    for (int b = threadIdx.x; b < H1_BINS; b += blockDim.x) {
        unsigned int c = sh[b] + sh[b + H1_BINS];
        if (c) atomicAdd(&g_hist1[b], c);
    }
}

// ---------------------------------------------------------------------------
__device__ __forceinline__ unsigned int block_incl_scan(unsigned int v, unsigned int* sh) {
    int t = threadIdx.x;
    sh[t] = v;
    __syncthreads();
    for (int off = 1; off < blockDim.x; off <<= 1) {
        unsigned int add = (t >= off) ? sh[t - off] : 0u;
        __syncthreads();
        sh[t] += add;
        __syncthreads();
    }
    return sh[t];
}

// select level 1: 12-bit bin holding rank-k (descending)
__global__ void select1_k(const int* __restrict__ kp) {
    __shared__ unsigned int sh[1024];
    const unsigned int k = (unsigned int)(*kp);
    int t = threadIdx.x;
    unsigned int c[4], s = 0;
#pragma unroll
    for (int j = 0; j < 4; j++) { c[j] = g_hist1[4095 - (4 * t + j)]; s += c[j]; }
    unsigned int incl = block_incl_scan(s, sh);
    unsigned int excl = incl - s;
    if (excl < k && k <= incl) {
        unsigned int cum = excl;
#pragma unroll
        for (int j = 0; j < 4; j++) {
            if (cum + c[j] >= k) { g_prefix12 = 4095 - (4 * t + j); g_k1 = k - cum; break; }
            cum += c[j];
        }
    }
}

// ---------------------------------------------------------------------------
// pass B: 20-bit histogram inside selected 12-bit bin (sparse global atomics)
// ---------------------------------------------------------------------------
__global__ void __launch_bounds__(256) hist2_k(int n4) {
    const unsigned int pfx = g_prefix12;
    const int stride = gridDim.x * blockDim.x;
    int i = blockIdx.x * blockDim.x + threadIdx.x;
    for (; i + stride < n4; i += 2 * stride) {
        uint4 a = ((const uint4*)g_keys)[i];
        uint4 b = ((const uint4*)g_keys)[i + stride];
        if ((a.x >> 20) == pfx) atomicAdd(&g_hist2[a.x & 0xFFFFFu], 1u);
        if ((a.y >> 20) == pfx) atomicAdd(&g_hist2[a.y & 0xFFFFFu], 1u);
        if ((a.z >> 20) == pfx) atomicAdd(&g_hist2[a.z & 0xFFFFFu], 1u);
        if ((a.w >> 20) == pfx) atomicAdd(&g_hist2[a.w & 0xFFFFFu], 1u);
        if ((b.x >> 20) == pfx) atomicAdd(&g_hist2[b.x & 0xFFFFFu], 1u);
        if ((b.y >> 20) == pfx) atomicAdd(&g_hist2[b.y & 0xFFFFFu], 1u);
        if ((b.z >> 20) == pfx) atomicAdd(&g_hist2[b.z & 0xFFFFFu], 1u);
        if ((b.w >> 20) == pfx) atomicAdd(&g_hist2[b.w & 0xFFFFFu], 1u);
    }
    for (; i < n4; i += stride) {
        uint4 a = ((const uint4*)g_keys)[i];
        if ((a.x >> 20) == pfx) atomicAdd(&g_hist2[a.x & 0xFFFFFu], 1u);
        if ((a.y >> 20) == pfx) atomicAdd(&g_hist2[a.y & 0xFFFFFu], 1u);
        if ((a.z >> 20) == pfx) atomicAdd(&g_hist2[a.z & 0xFFFFFu], 1u);
        if ((a.w >> 20) == pfx) atomicAdd(&g_hist2[a.w & 0xFFFFFu], 1u);
    }
}

// chunk sums of hist2 (1024 chunks of 1024 bins)
__global__ void chunksum2_k() {
    __shared__ unsigned int sh[256];
    int b = blockIdx.x;
    unsigned int s = 0;
    for (int j = threadIdx.x; j < 1024; j += 256) s += g_hist2[b * 1024 + j];
    sh[threadIdx.x] = s;
    __syncthreads();
    for (int off = 128; off > 0; off >>= 1) {
        if (threadIdx.x < off) sh[threadIdx.x] += sh[threadIdx.x + off];
        __syncthreads();
    }
    if (threadIdx.x == 0) g_csum2[b] = sh[0];
}

// select level 2: exact threshold key T and r = #(==T) to include
__global__ void select2_k() {
    __shared__ unsigned int sh[1024];
    __shared__ unsigned int s_chunk, s_k2;
    int t = threadIdx.x;
    const unsigned int k1 = g_k1;
    unsigned int s = g_csum2[1023 - t];
    unsigned int incl = block_incl_scan(s, sh);
    unsigned int excl = incl - s;
    if (excl < k1 && k1 <= incl) { s_chunk = 1023 - t; s_k2 = k1 - excl; }
    __syncthreads();
    const unsigned int a = s_chunk;
    const unsigned int k2 = s_k2;
    unsigned int bin = a * 1024 + 1023 - t;
    unsigned int cb = g_hist2[bin];
    __syncthreads();
    unsigned int incl2 = block_incl_scan(cb, sh);
    unsigned int excl2 = incl2 - cb;
    if (excl2 < k2 && k2 <= incl2) {
        g_T = (g_prefix12 << 20) | bin;
        g_r = k2 - excl2;
    }
}

// ---------------------------------------------------------------------------
// pass D: final output. key>T -> mask 1; key<T -> mask 0; key==T -> record tie,
// write provisional mask=0 result (fixed up afterwards).
// ---------------------------------------------------------------------------
__device__ __forceinline__ float out_elem(unsigned int key, int idx, float u0, float u1,
                                          unsigned int T, int tr) {
    float m = (key > T) ? 1.0f : 0.0f;
    if (key == T) {
        unsigned int p = atomicAdd(&g_tie_cnt, 1u);
        if (p < TIE_CAP) g_tie_idx[p] = idx;
        m = 0.0f;   // provisional; fixup_k corrects included ties
    }
    if (!tr) return m;
    return (m + gum(u1) > gum(u0)) ? 1.0f : 0.0f;
}

__global__ void __launch_bounds__(256) final_k(
        const float* __restrict__ u2,
        const int* __restrict__ training,
        float* __restrict__ out, int n4) {
    const unsigned int T = g_T;
    const int tr = *training;
    const int stride = gridDim.x * blockDim.x;
    int i = blockIdx.x * blockDim.x + threadIdx.x;
    for (; i + stride < n4; i += 2 * stride) {
        uint4 k0 = __ldcs((const uint4*)g_keys + i);
        float4 a0 = __ldcs((const float4*)u2 + 2 * i);
        float4 b0 = __ldcs((const float4*)u2 + 2 * i + 1);
        uint4 k1 = __ldcs((const uint4*)g_keys + i + stride);
        float4 a1 = __ldcs((const float4*)u2 + 2 * (i + stride));
        float4 b1 = __ldcs((const float4*)u2 + 2 * (i + stride) + 1);
        float4 o0, o1;
        o0.x = out_elem(k0.x, 4 * i + 0, a0.x, a0.y, T, tr);
        o0.y = out_elem(k0.y, 4 * i + 1, a0.z, a0.w, T, tr);
        o0.z = out_elem(k0.z, 4 * i + 2, b0.x, b0.y, T, tr);
        o0.w = out_elem(k0.w, 4 * i + 3, b0.z, b0.w, T, tr);
        int j = i + stride;
        o1.x = out_elem(k1.x, 4 * j + 0, a1.x, a1.y, T, tr);
        o1.y = out_elem(k1.y, 4 * j + 1, a1.z, a1.w, T, tr);
        o1.z = out_elem(k1.z, 4 * j + 2, b1.x, b1.y, T, tr);
        o1.w = out_elem(k1.w, 4 * j + 3, b1.z, b1.w, T, tr);
        __stcs((float4*)out + i, o0);
        __stcs((float4*)out + j, o1);
    }
    for (; i < n4; i += stride) {
        uint4 kk = __ldcs((const uint4*)g_keys + i);
        float4 a = __ldcs((const float4*)u2 + 2 * i);
        float4 b = __ldcs((const float4*)u2 + 2 * i + 1);
        float4 o;
        o.x = out_elem(kk.x, 4 * i + 0, a.x, a.y, T, tr);
        o.y = out_elem(kk.y, 4 * i + 1, a.z, a.w, T, tr);
        o.z = out_elem(kk.z, 4 * i + 2, b.x, b.y, T, tr);
        o.w = out_elem(kk.w, 4 * i + 3, b.z, b.w, T, tr);
        __stcs((float4*)out + i, o);
    }
}

// ---------------------------------------------------------------------------
// fixup: among ties (key==T), the r smallest indices belong to the mask.
// Rewrite their outputs with mask=1. Single block; tie count is tiny.
// ---------------------------------------------------------------------------
__global__ void fixup_k(const float* __restrict__ u2,
                        const int* __restrict__ training,
                        float* __restrict__ out, int n) {
    __shared__ int s_cnt;
    unsigned int m = g_tie_cnt;
    if (m > TIE_CAP) m = TIE_CAP;
    const unsigned int r = g_r;
    const int tr = *training;
    if (r == 0 || m == 0) return;
    // binary search: cutoff = smallest x such that #(tie_idx <= x) >= r
    int lo = 0, hi = n - 1;
    while (lo < hi) {
        int mid = lo + (hi - lo) / 2;
        if (threadIdx.x == 0) s_cnt = 0;
        __syncthreads();
        int c = 0;
        for (unsigned int j = threadIdx.x; j < m; j += blockDim.x)
            if (g_tie_idx[j] <= mid) c++;
        if (c) atomicAdd(&s_cnt, c);
        __syncthreads();
        if (s_cnt >= (int)r) hi = mid; else lo = mid + 1;
        __syncthreads();
    }
    int cutoff = lo;
    // rewrite included ties with mask = 1
    for (unsigned int j = threadIdx.x; j < m; j += blockDim.x) {
        int idx = g_tie_idx[j];
        if (idx <= cutoff) {
            float v = 1.0f;
            if (tr) {
                float g0 = gum(u2[2 * idx]);
                float g1 = gum(u2[2 * idx + 1]);
                v = (1.0f + g1 > g0) ? 1.0f : 0.0f;
            }
            out[idx] = v;
        }
    }
}

// ---------------------------------------------------------------------------
extern "C" void kernel_launch(void* const* d_in, const int* in_sizes, int n_in,
                              void* d_out, int out_size) {
    const float* mask_logits = (const float*)d_in[0];
    const float* u1          = (const float*)d_in[1];
    const float* u2          = (const float*)d_in[2];
    const int*   kp          = (const int*)d_in[3];
    const int*   training    = (const int*)d_in[4];
    float* out = (float*)d_out;

    const int n  = in_sizes[0];
    const int n4 = n / 4;

    reset_k<<<1024, 256>>>();
    score_hist_k<<<2048, 256>>>(mask_logits, u1, training, n4);
    select1_k<<<1, 1024>>>(kp);
    hist2_k<<<2048, 256>>>(n4);
    chunksum2_k<<<1024, 256>>>();
    select2_k<<<1, 1024>>>();
    final_k<<<4096, 256>>>(u2, training, out, n4);
    fixup_k<<<1, 1024>>>(u2, training, out, n);
}